// round 7
// baseline (speedup 1.0000x reference)
#include <cuda_runtime.h>
#include <math.h>

// ---------------- problem constants ----------------
#define NSEG   20        // 4 images x 5 levels
#define PADN   2048      // padded per-segment box storage (K<=2000)
#define SORTN  2048      // candidate sort size
#define NHBLK  260       // sum over segs of ceil(A/4096)
#define TOTC   4768      // 1000*4 + 768
#define NTILE  32        // max 64-box tiles per segment
#define NPAIR  528       // NTILE*(NTILE+1)/2 upper-triangle tile pairs

__constant__ int   c_A[5]   = {196608, 49152, 12288, 3072, 768};
__constant__ int   c_G[5]   = {256, 128, 64, 32, 16};
__constant__ float c_STR[5] = {4.f, 8.f, 16.f, 32.f, 64.f};
__constant__ int   c_K[5]   = {2000, 2000, 2000, 2000, 768};
__constant__ int   c_KP[5]  = {1000, 1000, 1000, 1000, 768};
// anchor w/h per ratio a in {0.5,1.0,2.0}, scale 8: S=base*8, w=S*sqrt(1/r), h=S*sqrt(r)
__constant__ float c_W[5][3] = {
  {(float)(256.0*1.4142135623730951),  256.f,  (float)(256.0*0.7071067811865476)},
  {(float)(512.0*1.4142135623730951),  512.f,  (float)(512.0*0.7071067811865476)},
  {(float)(1024.0*1.4142135623730951), 1024.f, (float)(1024.0*0.7071067811865476)},
  {(float)(2048.0*1.4142135623730951), 2048.f, (float)(2048.0*0.7071067811865476)},
  {(float)(4096.0*1.4142135623730951), 4096.f, (float)(4096.0*0.7071067811865476)}};
__constant__ float c_H[5][3] = {
  {(float)(256.0*0.7071067811865476),  256.f,  (float)(256.0*1.4142135623730951)},
  {(float)(512.0*0.7071067811865476),  512.f,  (float)(512.0*1.4142135623730951)},
  {(float)(1024.0*0.7071067811865476), 1024.f, (float)(1024.0*1.4142135623730951)},
  {(float)(2048.0*0.7071067811865476), 2048.f, (float)(2048.0*1.4142135623730951)},
  {(float)(4096.0*0.7071067811865476), 4096.f, (float)(4096.0*1.4142135623730951)}};

// exp matching XLA: jnp.exp(f32) lowers to libdevice __nv_expf, which is what
// CUDA expf() links to — bit-identical — UNLESS fast-math remaps expf->__expf.
// Under fast-math fall back to the correctly-rounded double route (immune).
__device__ __forceinline__ float exp_match(float x)
{
#if defined(__USE_FAST_MATH__) || defined(__FAST_MATH__)
    return (float)exp((double)x);
#else
    return expf(x);
#endif
}

// ---------------- device scratch ----------------
__device__ unsigned           g_hist[NSEG][4096];
__device__ unsigned           g_pref[NSEG];
__device__ int                g_rem[NSEG];
__device__ int                g_cnt[NSEG];
__device__ unsigned long long g_cand[NSEG][SORTN];
__device__ float              g_score[NSEG][PADN];
__device__ float4             g_boxes[NSEG][PADN];
__device__ unsigned long long g_mask[NSEG][PADN][32];   // ~10.5 MB
__device__ float              g_lscore[NSEG][1024];
__device__ int                g_lsrc[NSEG][1024];

struct KParams {
    const float* probs[5];
    const float* regs[5];
    const float* info;
};

__device__ __forceinline__ void blk_to_seg(int blk, int& seg, int& base)
{
    int s = 0;
    for (s = 0; s < NSEG; s++) {
        int ch = (c_A[s % 5] + 4095) >> 12;
        if (blk < ch) break;
        blk -= ch;
    }
    seg = s;
    base = blk << 12;
}

// warp-aggregated shared-histogram increment: lanes sharing a bucket elect a
// leader which adds popc once (hot exponent buckets otherwise serialize ATOMS).
__device__ __forceinline__ void agg_inc(unsigned* h, unsigned bucket)
{
    unsigned mask = __match_any_sync(0xffffffffu, bucket);
    int leader = __ffs(mask) - 1;
    if ((int)(threadIdx.x & 31u) == leader)
        atomicAdd(&h[bucket], (unsigned)__popc(mask));
}

// ---------------- kernel 1a/1b: grid-wide 12-bit histogram (2 rounds) ----------------
__global__ __launch_bounds__(256) void k_hist(KParams P, int round)
{
    int seg, base;
    blk_to_seg(blockIdx.x, seg, base);
    const int l = seg % 5, b = seg / 5;
    const int A = c_A[l];
    const float4* sc4 = (const float4*)(P.probs[l] + (size_t)2 * A * b);

    __shared__ unsigned h[4096];
    for (int k = threadIdx.x; k < 4096; k += 256) h[k] = 0u;
    __syncthreads();

    const unsigned pref = g_pref[seg];
    // 4096 anchors per block = 2048 float4 (2 anchors each): 8 iters x 256 thr
    for (int k = 0; k < 8; k++) {
        int i4 = (base >> 1) + k * 256 + threadIdx.x;
        bool valid = (2 * i4 < A);
        float4 v = valid ? sc4[i4] : make_float4(0.f, 0.f, 0.f, 0.f);
        unsigned u0 = __float_as_uint(v.x);   // anchor 2*i4   score
        unsigned u1 = __float_as_uint(v.z);   // anchor 2*i4+1 score
        if (round == 0) {
            unsigned b0 = u0 >> 20, b1 = u1 >> 20;
            unsigned act = __ballot_sync(0xffffffffu, valid);
            if (act == 0xffffffffu) {
                agg_inc(h, b0);
                agg_inc(h, b1);
            } else if (valid) {
                atomicAdd(&h[b0], 1u);
                atomicAdd(&h[b1], 1u);
            }
        } else if (valid) {
            if ((u0 >> 20) == pref) atomicAdd(&h[(u0 >> 8) & 0xFFFu], 1u);
            if ((u1 >> 20) == pref) atomicAdd(&h[(u1 >> 8) & 0xFFFu], 1u);
        }
    }
    __syncthreads();
    for (int k = threadIdx.x; k < 4096; k += 256) {
        unsigned v = h[k];
        if (v) atomicAdd(&g_hist[seg][k], v);
    }
}

// ---------------- kernel 2: per-segment threshold from histogram (also re-zeros) ----------------
__global__ __launch_bounds__(256) void k_thresh(int round)
{
    const int seg = blockIdx.x;
    const int l = seg % 5;
    const int A = c_A[l], K = c_K[l];

    __shared__ unsigned sh[4096];
    __shared__ unsigned gsum[256];
    const int tid = threadIdx.x;

    unsigned mysum = 0;
    #pragma unroll 4
    for (int k2 = 0; k2 < 16; k2++) {
        int bb = tid * 16 + k2;
        unsigned v = g_hist[seg][bb];
        sh[bb] = v;
        mysum += v;
        g_hist[seg][bb] = 0u;    // re-zero for next round / next replay
    }
    gsum[tid] = mysum;
    __syncthreads();

    if (tid == 0) {
        if (A <= K) {
            g_pref[seg] = 0u;
            g_rem[seg] = K;
            if (round == 1) g_cnt[seg] = 0;
        } else {
            int rem = (round == 0) ? K : g_rem[seg];
            unsigned cum = 0;
            int grp = 0;
            for (int gi = 255; gi >= 0; gi--) {
                unsigned c = gsum[gi];
                if (cum + c >= (unsigned)rem) { grp = gi; break; }
                cum += c;
            }
            int v = grp * 16;
            for (int bb = grp * 16 + 15; bb >= grp * 16; bb--) {
                unsigned c = sh[bb];
                if (cum + c >= (unsigned)rem) { v = bb; break; }
                cum += c;
            }
            unsigned pref = (round == 0) ? (unsigned)v
                                         : ((g_pref[seg] << 12) | (unsigned)v);
            g_pref[seg] = pref;
            g_rem[seg] = rem - (int)cum;
            if (round == 1) g_cnt[seg] = 0;
        }
    }
}

// ---------------- kernel 3: grid-wide compact of candidates >= 24-bit prefix ----------------
__global__ __launch_bounds__(256) void k_compact(KParams P)
{
    int seg, base;
    blk_to_seg(blockIdx.x, seg, base);
    const int l = seg % 5, b = seg / 5;
    const int A = c_A[l];
    const float4* sc4 = (const float4*)(P.probs[l] + (size_t)2 * A * b);
    const unsigned pref = g_pref[seg];    // A<=K segs have pref==0 -> all pass

    for (int k = 0; k < 8; k++) {
        int i4 = (base >> 1) + k * 256 + threadIdx.x;
        if (2 * i4 < A) {
            float4 v = sc4[i4];
            unsigned u0 = __float_as_uint(v.x);
            unsigned u1 = __float_as_uint(v.z);
            if ((u0 >> 8) >= pref) {
                int p = atomicAdd(&g_cnt[seg], 1);
                if (p < SORTN)
                    g_cand[seg][p] = ((unsigned long long)u0 << 32)
                                   | (unsigned)(~(unsigned)(2 * i4));
            }
            if ((u1 >> 8) >= pref) {
                int p = atomicAdd(&g_cnt[seg], 1);
                if (p < SORTN)
                    g_cand[seg][p] = ((unsigned long long)u1 << 32)
                                   | (unsigned)(~(unsigned)(2 * i4 + 1));
            }
        }
    }
}

// ---------------- kernel 4: per-segment bitonic sort 2048 + decode/clip top-K ----------------
__global__ __launch_bounds__(1024) void k_sortdecode(KParams P)
{
    const int seg = blockIdx.x;
    const int b = seg / 5, l = seg % 5;
    const int A = c_A[l], K = c_K[l], g = c_G[l];

    __shared__ unsigned long long cand[SORTN];
    const int tid = threadIdx.x;

    int cnt = g_cnt[seg];
    if (cnt > SORTN) cnt = SORTN;
    for (int i = tid; i < SORTN; i += 1024)
        cand[i] = (i < cnt) ? g_cand[seg][i] : 0ull;
    __syncthreads();

    // descending bitonic; keys unique ((score bits)<<32 | ~idx) => stable wrt index
    for (int k = 2; k <= SORTN; k <<= 1) {
        for (int j = k >> 1; j > 0; j >>= 1) {
            for (int i = tid; i < SORTN; i += 1024) {
                int ixj = i ^ j;
                if (ixj > i) {
                    bool desc = ((i & k) == 0);
                    unsigned long long a = cand[i], bb = cand[ixj];
                    if (desc ? (a < bb) : (a > bb)) { cand[i] = bb; cand[ixj] = a; }
                }
            }
            __syncthreads();
        }
    }

    const float* rg = P.regs[l] + (size_t)4 * A * b;
    const float hImg = P.info[b * 3 + 0];
    const float wImg = P.info[b * 3 + 1];
    const float xmax = __fsub_rn(wImg, 1.f);
    const float ymax = __fsub_rn(hImg, 1.f);
    const float strd = c_STR[l];

    for (int jj = tid; jj < PADN; jj += 1024) {
        if (jj < K) {
            unsigned long long key = cand[jj];
            if (key == 0ull) {   // impossible by construction; memory-safety guard
                g_score[seg][jj] = -1e30f;
                g_boxes[seg][jj] = make_float4(0.f, 0.f, 0.f, 0.f);
                continue;
            }
            unsigned u = (unsigned)(key >> 32);
            int idx = (int)(~(unsigned)key);
            g_score[seg][jj] = __uint_as_float(u);

            int a = idx % 3;
            int cell = idx / 3;
            int col = cell % g, row = cell / g;
            // exact-mirror of reference arithmetic: no FMA contraction, IEEE rn
            float cx0 = __fmul_rn(__fadd_rn((float)col, 0.5f), strd);
            float cy0 = __fmul_rn(__fadd_rn((float)row, 0.5f), strd);
            float w0 = c_W[l][a], h0 = c_H[l][a];
            float x1a = __fsub_rn(cx0, __fmul_rn(0.5f, w0));
            float x2a = __fadd_rn(cx0, __fmul_rn(0.5f, w0));
            float y1a = __fsub_rn(cy0, __fmul_rn(0.5f, h0));
            float y2a = __fadd_rn(cy0, __fmul_rn(0.5f, h0));
            float wa = __fsub_rn(x2a, x1a);
            float ha = __fsub_rn(y2a, y1a);
            float cxa = __fadd_rn(x1a, __fmul_rn(0.5f, wa));
            float cya = __fadd_rn(y1a, __fmul_rn(0.5f, ha));

            const float* rr = rg + (size_t)4 * idx;
            float dx = rr[0], dy = rr[1], dw = rr[2], dh = rr[3];
            float cx = __fadd_rn(__fmul_rn(dx, wa), cxa);
            float cy = __fadd_rn(__fmul_rn(dy, ha), cya);
            float w = __fmul_rn(exp_match(dw), wa);   // libdevice __nv_expf = XLA
            float h = __fmul_rn(exp_match(dh), ha);
            float x1 = __fsub_rn(cx, __fmul_rn(0.5f, w));
            float y1 = __fsub_rn(cy, __fmul_rn(0.5f, h));
            float x2 = __fadd_rn(cx, __fmul_rn(0.5f, w));
            float y2 = __fadd_rn(cy, __fmul_rn(0.5f, h));
            x1 = fminf(fmaxf(x1, 0.f), xmax);
            x2 = fminf(fmaxf(x2, 0.f), xmax);
            y1 = fminf(fmaxf(y1, 0.f), ymax);
            y2 = fminf(fmaxf(y2, 0.f), ymax);
            g_boxes[seg][jj] = make_float4(x1, y1, x2, y2);
        } else {
            g_boxes[seg][jj] = make_float4(0.f, 0.f, 0.f, 0.f);  // pad: iou==0 vs anything
        }
    }
}

// ---------------- kernel 5: suppression bitmask (upper triangle, specialized) ----------------
// DIAG=false (cc>rc): no jj>lo guard in the inner loop — the hot path.
template<bool DIAG>
__device__ __forceinline__ unsigned long long mask_row(
    const float4 bi, const float ai,
    const float4* __restrict__ bj, const float* __restrict__ aj, const int lo)
{
    const float cNext = __uint_as_float(0x3F333334u);  // nextafterf(0.7f)
    unsigned long long bits = 0ull;
    #pragma unroll 8
    for (int jj = 0; jj < 64; jj++) {
        if (!DIAG || jj > lo) {
            float4 B = bj[jj];
            float xx1 = fmaxf(bi.x, B.x), yy1 = fmaxf(bi.y, B.y);
            float xx2 = fminf(bi.z, B.z), yy2 = fminf(bi.w, B.w);
            float ww = fmaxf(__fsub_rn(xx2, xx1), 0.f);
            float hh = fmaxf(__fsub_rn(yy2, yy1), 0.f);
            float inter = __fmul_rn(ww, hh);
            float uni = fmaxf(__fsub_rn(__fadd_rn(ai, aj[jj]), inter), 1e-9f);
            // iou > 0.7f, bit-identical to div.rn compare, without the div:
            // fmaf sign is exact for (inter - c*uni); only the half-ulp band
            // (0.7f, nextafter(0.7f)) needs the actual IEEE division.
            bool sup = false;
            float dlo = fmaf(-0.7f, uni, inter);
            if (dlo > 0.f) {
                float dhi = fmaf(-cNext, uni, inter);
                sup = (dhi >= 0.f) || (__fdiv_rn(inter, uni) > 0.7f);
            }
            if (sup) bits |= (1ull << jj);
        }
    }
    return bits;
}

__global__ void k_mask()
{
    const int seg = blockIdx.y;
    const int l = seg % 5;
    const int n = c_K[l];

    // triangular decode of linear pair index -> (rc, cc), cc >= rc
    int p = blockIdx.x, rc = 0, rowlen = NTILE;
    while (p >= rowlen) { p -= rowlen; rowlen--; rc++; }
    const int cc = rc + p;
    if (cc * 64 >= n) return;    // implies rc*64 < n too when reached

    __shared__ float4 bj[64];
    __shared__ float aj[64];
    const int t = threadIdx.x;
    const int j0 = cc * 64;
    {
        float4 B = g_boxes[seg][j0 + t];       // padded rows are zero boxes
        bj[t] = B;
        aj[t] = __fmul_rn(fmaxf(__fsub_rn(B.z, B.x), 0.f),
                          fmaxf(__fsub_rn(B.w, B.y), 0.f));
    }
    __syncthreads();

    const int i = rc * 64 + t;
    if (i < n) {
        float4 bi = g_boxes[seg][i];
        float ai = __fmul_rn(fmaxf(__fsub_rn(bi.z, bi.x), 0.f),
                             fmaxf(__fsub_rn(bi.w, bi.y), 0.f));
        unsigned long long bits = (rc == cc)
            ? mask_row<true >(bi, ai, bj, aj, i - j0)
            : mask_row<false>(bi, ai, bj, aj, 0);
        g_mask[seg][i][cc] = bits;
    }
}

// ---------------- kernel 6: greedy NMS scan + stable partition ----------------
// Per word: bit-parallel fast path (no candidate-on-candidate suppression ->
// keep all, zero serial walk), rare slow path = lane-0 walk. Forward apply is
// striped across 4 warps (bpos%4==warp) to cut L2 latency chains 4x.
__global__ __launch_bounds__(128) void k_reduce()
{
    const int seg = blockIdx.x;
    const int l = seg % 5;
    const int n = c_K[l];
    const int kpn = c_KP[l];
    const int nW = (n + 63) >> 6;

    __shared__ unsigned long long diagAll[32][64];  // 16 KB: all diagonal blocks
    __shared__ unsigned long long rem[32], kp[32];
    __shared__ unsigned long long sOR[4][32];
    __shared__ unsigned long long s_kw;
    __shared__ int wp[32];
    __shared__ int s_numKept;

    const int tid = threadIdx.x;
    const int lane = tid & 31;
    const int wg = tid >> 5;

    // cooperative preload of all diagonal blocks (fully MLP-pipelined)
    for (int idx = tid; idx < nW * 64; idx += 128) {
        int w = idx >> 6, r = idx & 63;
        int row = w * 64 + r;
        diagAll[w][r] = (row < n) ? g_mask[seg][row][w] : 0ull;
    }
    if (tid < 32) {
        unsigned long long full = 0ull;
        int base = tid * 64;
        if (base < n) {
            int c2 = n - base; if (c2 > 64) c2 = 64;
            full = (c2 == 64) ? ~0ull : ((1ull << c2) - 1ull);
        }
        rem[tid] = full;
        kp[tid] = 0ull;
    }
    __syncthreads();

    const unsigned long long wgsel = 0x1111111111111111ull << wg;

    for (int w = 0; w < nW; w++) {
        // ---- phase A (warp 0): resolve word w ----
        if (wg == 0) {
            unsigned long long bits = rem[w];
            unsigned long long kw = 0ull;
            if (bits) {
                // S = OR of diag rows of all candidate bits (parallel)
                unsigned long long S = 0ull;
                if ((bits >> lane) & 1ull)        S |= diagAll[w][lane];
                if ((bits >> (lane + 32)) & 1ull) S |= diagAll[w][lane + 32];
                #pragma unroll
                for (int off = 16; off; off >>= 1)
                    S |= __shfl_xor_sync(0xffffffffu, S, off);
                if ((S & bits) == 0ull) {
                    kw = bits;                     // fast path: keep all candidates
                } else if (lane == 0) {            // slow path: exact greedy walk
                    unsigned long long bb = bits;
                    while (bb) {
                        int bpos = __ffsll((long long)bb) - 1;
                        kw |= (1ull << bpos);
                        bb &= ~(diagAll[w][bpos] | (1ull << bpos));
                    }
                }
                kw = __shfl_sync(0xffffffffu, kw, 0);
            }
            if (lane == 0) { kp[w] = kw; s_kw = kw; }
        }
        __syncthreads();

        // ---- phase B (all 4 warps): apply kept rows to future words ----
        const unsigned long long kw = s_kw;
        unsigned long long acc = 0ull;
        if (kw && lane > w && lane < nW) {
            unsigned long long sel = kw & wgsel;   // this warp's bit stripe
            while (sel) {
                int bpos = __ffsll((long long)sel) - 1;
                sel &= sel - 1ull;
                acc |= g_mask[seg][w * 64 + bpos][lane];
            }
        }
        sOR[wg][lane] = acc;
        __syncthreads();

        // ---- phase C (warp 0): fold partials into rem ----
        if (wg == 0 && lane > w && lane < nW) {
            rem[lane] &= ~((sOR[0][lane] | sOR[1][lane]) |
                           (sOR[2][lane] | sOR[3][lane]));
        }
        __syncwarp();   // warp-0 cross-lane rem visibility for next phase A
    }

    // ---- stable partition (warp 0): kept first, then suppressed (score -1) ----
    if (wg == 0) {
        int own = __popcll(kp[lane]);
        int p = own;
        for (int o = 1; o < 32; o <<= 1) {
            int v = __shfl_up_sync(0xffffffffu, p, o);
            if (lane >= o) p += v;
        }
        wp[lane] = p - own;          // exclusive prefix
        if (lane == 31) s_numKept = p;
        __syncwarp();
        const int numKept = s_numKept;

        for (int j = lane; j < n; j += 32) {
            int w = j >> 6, bpos = j & 63;
            unsigned long long word = kp[w];
            bool kept = (word >> bpos) & 1ull;
            int rank = wp[w] + __popcll(word & ((1ull << bpos) - 1ull));
            int pos = kept ? rank : (numKept + (j - rank));
            if (pos < kpn) {
                g_lscore[seg][pos] = kept ? g_score[seg][j] : -1.0f;
                g_lsrc[seg][pos] = j;
            }
        }
    }
}

// ---------------- kernel 7: cross-level top-1000 via rank-by-binary-search ----------------
__global__ __launch_bounds__(1024) void k_final(float* __restrict__ out)
{
    __shared__ unsigned long long keys[TOTC];  // 37.3 KB
    const int b = blockIdx.x;
    const int tid = threadIdx.x;

    for (int c = tid; c < TOTC; c += 1024) {
        int l = c / 1000, pos = c - l * 1000;   // level 4: c in [4000,4768)
        float s = g_lscore[b * 5 + l][pos];
        unsigned u = __float_as_uint(s);
        unsigned ob = (u & 0x80000000u) ? ~u : (u | 0x80000000u);  // order-preserving
        keys[c] = ((unsigned long long)ob << 32) | (unsigned)(~(unsigned)c);
    }
    __syncthreads();

    for (int c = tid; c < TOTC; c += 1024) {
        const unsigned long long Ke = keys[c];
        const int l = c / 1000, pos = c - l * 1000;
        int rank = pos;                         // own list sorted desc, keys unique
        #pragma unroll
        for (int l2 = 0; l2 < 5; l2++) {
            if (l2 == l) continue;
            int lo = 0, hi = c_KP[l2];
            const int base = l2 * 1000;
            while (lo < hi) {
                int mid = (lo + hi) >> 1;
                if (keys[base + mid] > Ke) lo = mid + 1; else hi = mid;
            }
            rank += lo;
        }
        if (rank < 1000) {
            float4 bx = make_float4(0.f, 0.f, 0.f, 0.f);
            if ((unsigned)(Ke >> 32) >= 0x80000000u) {   // score >= 0.0
                int src = g_lsrc[b * 5 + l][pos];
                bx = g_boxes[b * 5 + l][src];
            }
            float* o = out + ((size_t)b * 1000 + rank) * 5;
            o[0] = (float)b;
            o[1] = bx.x; o[2] = bx.y; o[3] = bx.z; o[4] = bx.w;
        }
    }
}

// ---------------- launch ----------------
extern "C" void kernel_launch(void* const* d_in, const int* in_sizes, int n_in,
                              void* d_out, int out_size)
{
    // Bind inputs by element count (all 11 sizes are distinct) — robust to
    // metadata ordering (setup_inputs interleaves probs/reg).
    static const int A[5] = {196608, 49152, 12288, 3072, 768};
    KParams P;
    P.info = nullptr;
    for (int l = 0; l < 5; l++) { P.probs[l] = nullptr; P.regs[l] = nullptr; }
    for (int i = 0; i < n_in; i++) {
        int s = in_sizes[i];
        const float* p = (const float*)d_in[i];
        if (s == 12) { P.info = p; continue; }
        for (int l = 0; l < 5; l++) {
            if (s == 8 * A[l])  P.probs[l] = p;
            if (s == 16 * A[l]) P.regs[l]  = p;
        }
    }
    float* out = (float*)d_out;

    k_hist<<<NHBLK, 256>>>(P, 0);
    k_thresh<<<NSEG, 256>>>(0);
    k_hist<<<NHBLK, 256>>>(P, 1);
    k_thresh<<<NSEG, 256>>>(1);
    k_compact<<<NHBLK, 256>>>(P);
    k_sortdecode<<<NSEG, 1024>>>(P);
    k_mask<<<dim3(NPAIR, NSEG), 64>>>();
    k_reduce<<<NSEG, 128>>>();
    k_final<<<4, 1024>>>(out);
}

// round 10
// speedup vs baseline: 1.1722x; 1.1722x over previous
#include <cuda_runtime.h>
#include <math.h>

// ---------------- problem constants ----------------
#define NSEG   20        // 4 images x 5 levels
#define PADN   2048      // padded per-segment box storage (K<=2000)
#define SORTN  2048      // candidate sort size
#define NHBLK  260       // sum over segs of ceil(A/4096)
#define TOTC   4768      // 1000*4 + 768
#define NTILE  32        // max 64-box tiles per segment
#define NGRP   272       // sum over cc of ceil((cc+1)/2): 2-row-tile groups

__constant__ int   c_A[5]   = {196608, 49152, 12288, 3072, 768};
__constant__ int   c_G[5]   = {256, 128, 64, 32, 16};
__constant__ float c_STR[5] = {4.f, 8.f, 16.f, 32.f, 64.f};
__constant__ int   c_K[5]   = {2000, 2000, 2000, 2000, 768};
__constant__ int   c_KP[5]  = {1000, 1000, 1000, 1000, 768};
// anchor w/h per ratio a in {0.5,1.0,2.0}, scale 8: S=base*8, w=S*sqrt(1/r), h=S*sqrt(r)
__constant__ float c_W[5][3] = {
  {(float)(256.0*1.4142135623730951),  256.f,  (float)(256.0*0.7071067811865476)},
  {(float)(512.0*1.4142135623730951),  512.f,  (float)(512.0*0.7071067811865476)},
  {(float)(1024.0*1.4142135623730951), 1024.f, (float)(1024.0*0.7071067811865476)},
  {(float)(2048.0*1.4142135623730951), 2048.f, (float)(2048.0*0.7071067811865476)},
  {(float)(4096.0*1.4142135623730951), 4096.f, (float)(4096.0*0.7071067811865476)}};
__constant__ float c_H[5][3] = {
  {(float)(256.0*0.7071067811865476),  256.f,  (float)(256.0*1.4142135623730951)},
  {(float)(512.0*0.7071067811865476),  512.f,  (float)(512.0*1.4142135623730951)},
  {(float)(1024.0*0.7071067811865476), 1024.f, (float)(1024.0*1.4142135623730951)},
  {(float)(2048.0*0.7071067811865476), 2048.f, (float)(2048.0*1.4142135623730951)},
  {(float)(4096.0*0.7071067811865476), 4096.f, (float)(4096.0*1.4142135623730951)}};

// exp matching XLA: jnp.exp(f32) lowers to libdevice __nv_expf == CUDA expf,
// unless fast-math remaps expf->__expf; then use correctly-rounded double.
__device__ __forceinline__ float exp_match(float x)
{
#if defined(__USE_FAST_MATH__) || defined(__FAST_MATH__)
    return (float)exp((double)x);
#else
    return expf(x);
#endif
}

// ---------------- device scratch ----------------
__device__ unsigned           g_histA[NSEG][4096];
__device__ unsigned           g_histB[NSEG][4096];
__device__ int                g_cnt[NSEG];
__device__ unsigned long long g_cand[NSEG][SORTN];
__device__ float              g_score[NSEG][PADN];
__device__ float4             g_boxes[NSEG][PADN];
__device__ unsigned long long g_mask[NSEG][PADN][32];   // ~10.5 MB
__device__ float              g_lscore[NSEG][1024];
__device__ int                g_lsrc[NSEG][1024];

struct KParams {
    const float* probs[5];
    const float* regs[5];
    const float* info;
};

__device__ __forceinline__ void blk_to_seg(int blk, int& seg, int& base)
{
    int s = 0;
    for (s = 0; s < NSEG; s++) {
        int ch = (c_A[s % 5] + 4095) >> 12;
        if (blk < ch) break;
        blk -= ch;
    }
    seg = s;
    base = blk << 12;
}

// warp-aggregated shared-histogram increment
__device__ __forceinline__ void agg_inc(unsigned* h, unsigned bucket)
{
    unsigned mask = __match_any_sync(0xffffffffu, bucket);
    int leader = __ffs(mask) - 1;
    if ((int)(threadIdx.x & 31u) == leader)
        atomicAdd(&h[bucket], (unsigned)__popc(mask));
}

// Block-wide 12-bit top-bucket selection from a 4096-bin global histogram.
// Requires blockDim.x == 256 and 1 <= rem <= total(gH). On return (all
// threads, post-barrier): s_out[0] = bucket v, s_out[1] = count strictly
// above v. Clobbers sh[4096], csuf[257].
__device__ void scan12(const unsigned* __restrict__ gH, unsigned rem,
                       unsigned* sh, unsigned* csuf, unsigned* s_out)
{
    const int tid = threadIdx.x;
    unsigned mysum = 0;
    #pragma unroll
    for (int k2 = 0; k2 < 16; k2++) {
        unsigned v = gH[tid * 16 + k2];
        sh[tid * 16 + k2] = v;
        mysum += v;
    }
    csuf[tid] = mysum;
    if (tid == 0) csuf[256] = 0u;
    __syncthreads();

    // Hillis–Steele suffix sum over 256 chunk sums
    #pragma unroll
    for (int off = 1; off < 256; off <<= 1) {
        unsigned v = (tid + off < 256) ? csuf[tid + off] : 0u;
        __syncthreads();
        csuf[tid] += v;
        __syncthreads();
    }

    // exactly one boundary chunk: csuf[t] >= rem > csuf[t+1]
    if (csuf[tid] >= rem && csuf[tid + 1] < rem) {
        unsigned cum = csuf[tid + 1];
        int v = tid * 16;
        for (int bb = tid * 16 + 15; bb >= tid * 16; bb--) {
            unsigned c = sh[bb];
            if (cum + c >= rem) { v = bb; break; }
            cum += c;
        }
        s_out[0] = (unsigned)v;
        s_out[1] = cum;
    }
    __syncthreads();
}

// ---------------- kernel 1: grid-wide round-0 12-bit histogram ----------------
__global__ __launch_bounds__(256) void k_hist0(KParams P)
{
    int seg, base;
    blk_to_seg(blockIdx.x, seg, base);
    const int l = seg % 5, b = seg / 5;
    const int A = c_A[l];
    if (A <= c_K[l]) return;               // tiny segment: no selection needed
    const float4* sc4 = (const float4*)(P.probs[l] + (size_t)2 * A * b);

    __shared__ unsigned h[4096];
    for (int k = threadIdx.x; k < 4096; k += 256) h[k] = 0u;
    __syncthreads();

    for (int k = 0; k < 8; k++) {
        int i4 = (base >> 1) + k * 256 + threadIdx.x;
        bool valid = (2 * i4 < A);
        float4 v = valid ? sc4[i4] : make_float4(0.f, 0.f, 0.f, 0.f);
        unsigned b0 = __float_as_uint(v.x) >> 20;
        unsigned b1 = __float_as_uint(v.z) >> 20;
        unsigned act = __ballot_sync(0xffffffffu, valid);
        if (act == 0xffffffffu) {
            agg_inc(h, b0);
            agg_inc(h, b1);
        } else if (valid) {
            atomicAdd(&h[b0], 1u);
            atomicAdd(&h[b1], 1u);
        }
    }
    __syncthreads();
    for (int k = threadIdx.x; k < 4096; k += 256) {
        unsigned v = h[k];
        if (v) atomicAdd(&g_histA[seg][k], v);
    }
}

// ---------------- kernel 2: fused threshold(round0) + round-1 histogram ----------------
__global__ __launch_bounds__(256) void k_hist1(KParams P)
{
    int seg, base;
    blk_to_seg(blockIdx.x, seg, base);
    const int l = seg % 5, b = seg / 5;
    const int A = c_A[l], K = c_K[l];
    if (A <= K) return;
    const float4* sc4 = (const float4*)(P.probs[l] + (size_t)2 * A * b);

    __shared__ unsigned sh[4096];
    __shared__ unsigned csuf[257];
    __shared__ unsigned s_out[2];

    scan12(g_histA[seg], (unsigned)K, sh, csuf, s_out);
    const unsigned pref = s_out[0];

    // reuse sh as local round-1 histogram
    for (int k = threadIdx.x; k < 4096; k += 256) sh[k] = 0u;
    __syncthreads();

    for (int k = 0; k < 8; k++) {
        int i4 = (base >> 1) + k * 256 + threadIdx.x;
        if (2 * i4 < A) {
            float4 v = sc4[i4];
            unsigned u0 = __float_as_uint(v.x);
            unsigned u1 = __float_as_uint(v.z);
            if ((u0 >> 20) == pref) atomicAdd(&sh[(u0 >> 8) & 0xFFFu], 1u);
            if ((u1 >> 20) == pref) atomicAdd(&sh[(u1 >> 8) & 0xFFFu], 1u);
        }
    }
    __syncthreads();
    for (int k = threadIdx.x; k < 4096; k += 256) {
        unsigned v = sh[k];
        if (v) atomicAdd(&g_histB[seg][k], v);
    }
}

// ---------------- kernel 3: fused threshold(round1) + compact ----------------
__global__ __launch_bounds__(256) void k_compact(KParams P)
{
    int seg, base;
    blk_to_seg(blockIdx.x, seg, base);
    const int l = seg % 5, b = seg / 5;
    const int A = c_A[l], K = c_K[l];
    const float4* sc4 = (const float4*)(P.probs[l] + (size_t)2 * A * b);

    __shared__ unsigned sh[4096];
    __shared__ unsigned csuf[257];
    __shared__ unsigned s_out[2];

    unsigned pref = 0u;                    // A<=K: all pass
    if (A > K) {
        scan12(g_histA[seg], (unsigned)K, sh, csuf, s_out);
        const unsigned v1 = s_out[0];
        const unsigned rem1 = (unsigned)K - s_out[1];
        scan12(g_histB[seg], rem1, sh, csuf, s_out);
        pref = (v1 << 12) | s_out[0];
    }

    for (int k = 0; k < 8; k++) {
        int i4 = (base >> 1) + k * 256 + threadIdx.x;
        if (2 * i4 < A) {
            float4 v = sc4[i4];
            unsigned u0 = __float_as_uint(v.x);
            unsigned u1 = __float_as_uint(v.z);
            if ((u0 >> 8) >= pref) {
                int p = atomicAdd(&g_cnt[seg], 1);
                if (p < SORTN)
                    g_cand[seg][p] = ((unsigned long long)u0 << 32)
                                   | (unsigned)(~(unsigned)(2 * i4));
            }
            if ((u1 >> 8) >= pref) {
                int p = atomicAdd(&g_cnt[seg], 1);
                if (p < SORTN)
                    g_cand[seg][p] = ((unsigned long long)u1 << 32)
                                   | (unsigned)(~(unsigned)(2 * i4 + 1));
            }
        }
    }
}

// ---------------- kernel 4: per-segment bitonic sort 2048 + decode/clip top-K ----------------
// Also re-zeroes g_histA/g_histB/g_cnt for the next graph replay.
__global__ __launch_bounds__(1024) void k_sortdecode(KParams P)
{
    const int seg = blockIdx.x;
    const int b = seg / 5, l = seg % 5;
    const int A = c_A[l], K = c_K[l], g = c_G[l];

    __shared__ unsigned long long cand[SORTN];
    const int tid = threadIdx.x;

    int cnt = g_cnt[seg];
    if (cnt > SORTN) cnt = SORTN;
    for (int i = tid; i < SORTN; i += 1024)
        cand[i] = (i < cnt) ? g_cand[seg][i] : 0ull;
    __syncthreads();

    // replay-state reset (all consumers of these ran in earlier kernels)
    for (int i = tid; i < 4096; i += 1024) {
        g_histA[seg][i] = 0u;
        g_histB[seg][i] = 0u;
    }
    if (tid == 0) g_cnt[seg] = 0;

    // descending bitonic; keys unique ((score bits)<<32 | ~idx) => stable wrt index
    for (int k = 2; k <= SORTN; k <<= 1) {
        for (int j = k >> 1; j > 0; j >>= 1) {
            for (int i = tid; i < SORTN; i += 1024) {
                int ixj = i ^ j;
                if (ixj > i) {
                    bool desc = ((i & k) == 0);
                    unsigned long long a = cand[i], bb = cand[ixj];
                    if (desc ? (a < bb) : (a > bb)) { cand[i] = bb; cand[ixj] = a; }
                }
            }
            __syncthreads();
        }
    }

    const float* rg = P.regs[l] + (size_t)4 * A * b;
    const float hImg = P.info[b * 3 + 0];
    const float wImg = P.info[b * 3 + 1];
    const float xmax = __fsub_rn(wImg, 1.f);
    const float ymax = __fsub_rn(hImg, 1.f);
    const float strd = c_STR[l];

    for (int jj = tid; jj < PADN; jj += 1024) {
        if (jj < K) {
            unsigned long long key = cand[jj];
            if (key == 0ull) {   // impossible by construction; memory-safety guard
                g_score[seg][jj] = -1e30f;
                g_boxes[seg][jj] = make_float4(0.f, 0.f, 0.f, 0.f);
                continue;
            }
            unsigned u = (unsigned)(key >> 32);
            int idx = (int)(~(unsigned)key);
            g_score[seg][jj] = __uint_as_float(u);

            int a = idx % 3;
            int cell = idx / 3;
            int col = cell % g, row = cell / g;
            // exact-mirror of reference arithmetic: no FMA contraction, IEEE rn
            float cx0 = __fmul_rn(__fadd_rn((float)col, 0.5f), strd);
            float cy0 = __fmul_rn(__fadd_rn((float)row, 0.5f), strd);
            float w0 = c_W[l][a], h0 = c_H[l][a];
            float x1a = __fsub_rn(cx0, __fmul_rn(0.5f, w0));
            float x2a = __fadd_rn(cx0, __fmul_rn(0.5f, w0));
            float y1a = __fsub_rn(cy0, __fmul_rn(0.5f, h0));
            float y2a = __fadd_rn(cy0, __fmul_rn(0.5f, h0));
            float wa = __fsub_rn(x2a, x1a);
            float ha = __fsub_rn(y2a, y1a);
            float cxa = __fadd_rn(x1a, __fmul_rn(0.5f, wa));
            float cya = __fadd_rn(y1a, __fmul_rn(0.5f, ha));

            const float* rr = rg + (size_t)4 * idx;
            float dx = rr[0], dy = rr[1], dw = rr[2], dh = rr[3];
            float cx = __fadd_rn(__fmul_rn(dx, wa), cxa);
            float cy = __fadd_rn(__fmul_rn(dy, ha), cya);
            float w = __fmul_rn(exp_match(dw), wa);
            float h = __fmul_rn(exp_match(dh), ha);
            float x1 = __fsub_rn(cx, __fmul_rn(0.5f, w));
            float y1 = __fsub_rn(cy, __fmul_rn(0.5f, h));
            float x2 = __fadd_rn(cx, __fmul_rn(0.5f, w));
            float y2 = __fadd_rn(cy, __fmul_rn(0.5f, h));
            x1 = fminf(fmaxf(x1, 0.f), xmax);
            x2 = fminf(fmaxf(x2, 0.f), xmax);
            y1 = fminf(fmaxf(y1, 0.f), ymax);
            y2 = fminf(fmaxf(y2, 0.f), ymax);
            g_boxes[seg][jj] = make_float4(x1, y1, x2, y2);
        } else {
            g_boxes[seg][jj] = make_float4(0.f, 0.f, 0.f, 0.f);  // pad: iou==0
        }
    }
}

// ---------------- kernel 5: suppression bitmask ----------------
// 128-thread blocks: one 64-box column tile in smem serves TWO row tiles.
template<bool DIAG>
__device__ __forceinline__ unsigned long long mask_row(
    const float4 bi, const float ai,
    const float4* __restrict__ bj, const float* __restrict__ aj, const int lo)
{
    const float cNext = __uint_as_float(0x3F333334u);  // nextafterf(0.7f)
    unsigned long long bits = 0ull;
    #pragma unroll 8
    for (int jj = 0; jj < 64; jj++) {
        if (!DIAG || jj > lo) {
            float4 B = bj[jj];
            float xx1 = fmaxf(bi.x, B.x), yy1 = fmaxf(bi.y, B.y);
            float xx2 = fminf(bi.z, B.z), yy2 = fminf(bi.w, B.w);
            float ww = fmaxf(__fsub_rn(xx2, xx1), 0.f);
            float hh = fmaxf(__fsub_rn(yy2, yy1), 0.f);
            float inter = __fmul_rn(ww, hh);
            float uni = fmaxf(__fsub_rn(__fadd_rn(ai, aj[jj]), inter), 1e-9f);
            // iou > 0.7f, bit-identical to div.rn compare, without the div.
            bool sup = false;
            float dlo = fmaf(-0.7f, uni, inter);
            if (dlo > 0.f) {
                float dhi = fmaf(-cNext, uni, inter);
                sup = (dhi >= 0.f) || (__fdiv_rn(inter, uni) > 0.7f);
            }
            if (sup) bits |= (1ull << jj);
        }
    }
    return bits;
}

__global__ __launch_bounds__(128) void k_mask()
{
    const int seg = blockIdx.y;
    const int l = seg % 5;
    const int n = c_K[l];

    // decode linear group index -> (rb, cc): for column tile cc, row-tile
    // groups rb = 0..ceil((cc+1)/2)-1 covering row tiles {2rb, 2rb+1} <= cc
    int p = blockIdx.x, cc = 0;
    while (p >= (cc >> 1) + 1) { p -= (cc >> 1) + 1; cc++; }
    const int rb = p;
    if (cc * 64 >= n) return;               // uniform per block, before any sync

    __shared__ float4 bj[64];
    __shared__ float aj[64];
    const int t = threadIdx.x;
    const int j0 = cc * 64;
    if (t < 64) {
        float4 B = g_boxes[seg][j0 + t];    // padded rows are zero boxes
        bj[t] = B;
        aj[t] = __fmul_rn(fmaxf(__fsub_rn(B.z, B.x), 0.f),
                          fmaxf(__fsub_rn(B.w, B.y), 0.f));
    }
    __syncthreads();

    const int rc = 2 * rb + (t >> 6);       // this half-block's row tile
    const int i = rc * 64 + (t & 63);
    if (rc <= cc && i < n) {
        float4 bi = g_boxes[seg][i];
        float ai = __fmul_rn(fmaxf(__fsub_rn(bi.z, bi.x), 0.f),
                             fmaxf(__fsub_rn(bi.w, bi.y), 0.f));
        unsigned long long bits = (rc == cc)
            ? mask_row<true >(bi, ai, bj, aj, i - j0)
            : mask_row<false>(bi, ai, bj, aj, 0);
        g_mask[seg][i][cc] = bits;
    }
}

// ---------------- kernel 6: greedy NMS scan + stable partition ----------------
// Phase A: exact parallel peeling. D = cur & ~OR{diag[b]:b in cur} is exactly
// the set greedy keeps at this stage; strike D's victims, repeat.
__global__ __launch_bounds__(128) void k_reduce()
{
    const int seg = blockIdx.x;
    const int l = seg % 5;
    const int n = c_K[l];
    const int kpn = c_KP[l];
    const int nW = (n + 63) >> 6;

    __shared__ unsigned long long diagAll[32][64];  // 16 KB: all diagonal blocks
    __shared__ unsigned long long rem[32], kp[32];
    __shared__ unsigned long long sOR[4][32];
    __shared__ unsigned long long s_kw;
    __shared__ int wp[32];
    __shared__ int s_numKept;

    const int tid = threadIdx.x;
    const int lane = tid & 31;
    const int wg = tid >> 5;

    for (int idx = tid; idx < nW * 64; idx += 128) {
        int w = idx >> 6, r = idx & 63;
        int row = w * 64 + r;
        diagAll[w][r] = (row < n) ? g_mask[seg][row][w] : 0ull;
    }
    if (tid < 32) {
        unsigned long long full = 0ull;
        int base = tid * 64;
        if (base < n) {
            int c2 = n - base; if (c2 > 64) c2 = 64;
            full = (c2 == 64) ? ~0ull : ((1ull << c2) - 1ull);
        }
        rem[tid] = full;
        kp[tid] = 0ull;
    }
    __syncthreads();

    const unsigned long long wgsel = 0x1111111111111111ull << wg;

    for (int w = 0; w < nW; w++) {
        // ---- phase A (warp 0): resolve word w via parallel peeling ----
        if (wg == 0) {
            unsigned long long cur = rem[w];
            unsigned long long kw = 0ull;
            const unsigned long long d0 = diagAll[w][lane];
            const unsigned long long d1 = diagAll[w][lane + 32];
            while (cur) {
                unsigned long long S = 0ull;
                if ((cur >> lane) & 1ull)        S |= d0;
                if ((cur >> (lane + 32)) & 1ull) S |= d1;
                #pragma unroll
                for (int off = 16; off; off >>= 1)
                    S |= __shfl_xor_sync(0xffffffffu, S, off);
                unsigned long long D = cur & ~S;    // kept this round (never empty)
                kw |= D;
                cur &= ~D;
                if (!cur) break;                    // no survivors -> skip 2nd reduce
                unsigned long long supD = 0ull;
                if ((D >> lane) & 1ull)        supD |= d0;
                if ((D >> (lane + 32)) & 1ull) supD |= d1;
                #pragma unroll
                for (int off = 16; off; off >>= 1)
                    supD |= __shfl_xor_sync(0xffffffffu, supD, off);
                cur &= ~supD;
            }
            if (lane == 0) { kp[w] = kw; s_kw = kw; }
        }
        __syncthreads();

        // ---- phase B (all 4 warps): apply kept rows to future words ----
        const unsigned long long kw = s_kw;
        unsigned long long acc = 0ull;
        if (kw && lane > w && lane < nW) {
            unsigned long long sel = kw & wgsel;   // this warp's bit stripe
            while (sel) {
                int bpos = __ffsll((long long)sel) - 1;
                sel &= sel - 1ull;
                acc |= g_mask[seg][w * 64 + bpos][lane];
            }
        }
        sOR[wg][lane] = acc;
        __syncthreads();

        // ---- phase C (warp 0): fold partials into rem ----
        if (wg == 0 && lane > w && lane < nW) {
            rem[lane] &= ~((sOR[0][lane] | sOR[1][lane]) |
                           (sOR[2][lane] | sOR[3][lane]));
        }
        __syncwarp();
    }

    // ---- stable partition (warp 0): kept first, then suppressed (score -1) ----
    if (wg == 0) {
        int own = __popcll(kp[lane]);
        int p = own;
        for (int o = 1; o < 32; o <<= 1) {
            int v = __shfl_up_sync(0xffffffffu, p, o);
            if (lane >= o) p += v;
        }
        wp[lane] = p - own;
        if (lane == 31) s_numKept = p;
        __syncwarp();
        const int numKept = s_numKept;

        for (int j = lane; j < n; j += 32) {
            int w = j >> 6, bpos = j & 63;
            unsigned long long word = kp[w];
            bool kept = (word >> bpos) & 1ull;
            int rank = wp[w] + __popcll(word & ((1ull << bpos) - 1ull));
            int pos = kept ? rank : (numKept + (j - rank));
            if (pos < kpn) {
                g_lscore[seg][pos] = kept ? g_score[seg][j] : -1.0f;
                g_lsrc[seg][pos] = j;
            }
        }
    }
}

// ---------------- kernel 7: cross-level top-1000 via rank-by-binary-search ----------------
__global__ __launch_bounds__(1024) void k_final(float* __restrict__ out)
{
    __shared__ unsigned long long keys[TOTC];  // 37.3 KB
    const int b = blockIdx.x;
    const int tid = threadIdx.x;

    for (int c = tid; c < TOTC; c += 1024) {
        int l = c / 1000, pos = c - l * 1000;
        float s = g_lscore[b * 5 + l][pos];
        unsigned u = __float_as_uint(s);
        unsigned ob = (u & 0x80000000u) ? ~u : (u | 0x80000000u);
        keys[c] = ((unsigned long long)ob << 32) | (unsigned)(~(unsigned)c);
    }
    __syncthreads();

    for (int c = tid; c < TOTC; c += 1024) {
        const unsigned long long Ke = keys[c];
        const int l = c / 1000, pos = c - l * 1000;
        int rank = pos;
        #pragma unroll
        for (int l2 = 0; l2 < 5; l2++) {
            if (l2 == l) continue;
            int lo = 0, hi = c_KP[l2];
            const int base = l2 * 1000;
            while (lo < hi) {
                int mid = (lo + hi) >> 1;
                if (keys[base + mid] > Ke) lo = mid + 1; else hi = mid;
            }
            rank += lo;
        }
        if (rank < 1000) {
            float4 bx = make_float4(0.f, 0.f, 0.f, 0.f);
            if ((unsigned)(Ke >> 32) >= 0x80000000u) {
                int src = g_lsrc[b * 5 + l][pos];
                bx = g_boxes[b * 5 + l][src];
            }
            float* o = out + ((size_t)b * 1000 + rank) * 5;
            o[0] = (float)b;
            o[1] = bx.x; o[2] = bx.y; o[3] = bx.z; o[4] = bx.w;
        }
    }
}

// ---------------- launch ----------------
extern "C" void kernel_launch(void* const* d_in, const int* in_sizes, int n_in,
                              void* d_out, int out_size)
{
    static const int A[5] = {196608, 49152, 12288, 3072, 768};
    KParams P;
    P.info = nullptr;
    for (int l = 0; l < 5; l++) { P.probs[l] = nullptr; P.regs[l] = nullptr; }
    for (int i = 0; i < n_in; i++) {
        int s = in_sizes[i];
        const float* p = (const float*)d_in[i];
        if (s == 12) { P.info = p; continue; }
        for (int l = 0; l < 5; l++) {
            if (s == 8 * A[l])  P.probs[l] = p;
            if (s == 16 * A[l]) P.regs[l]  = p;
        }
    }
    float* out = (float*)d_out;

    k_hist0<<<NHBLK, 256>>>(P);
    k_hist1<<<NHBLK, 256>>>(P);
    k_compact<<<NHBLK, 256>>>(P);
    k_sortdecode<<<NSEG, 1024>>>(P);
    k_mask<<<dim3(NGRP, NSEG), 128>>>();
    k_reduce<<<NSEG, 128>>>();
    k_final<<<4, 1024>>>(out);
}